// round 5
// baseline (speedup 1.0000x reference)
#include <cuda_runtime.h>
#include <cstdint>
#include <cstddef>

#define BB 1024
#define FF 4096
#define DD 32
#define NT 5             // n-tiles of 8: n 0-31 = embed dims, 32 = bias, 33-39 = zero pad
#define MTILES 8
#define KSPLITS 16
#define K_PER_CTA 256
#define KC 32            // K per chunk
#define NCHUNK 8         // chunks per CTA
#define A_STRIDE 36      // smem floats per A row (conflict-free, 16B aligned)
#define B_STRIDE 40      // smem floats per B k-row (conflict-free, 16B aligned)

__device__ float g_s[(size_t)BB * DD];     // accumulated s[row][d] (static zero; self-zeroing)
__device__ float g_b[(size_t)BB];          // accumulated bias_term[row]
__device__ unsigned g_cnt[MTILES];         // per-mtile k-split arrival counters

__device__ __forceinline__ uint32_t smem_u32(const void* p) {
    uint32_t a;
    asm("{ .reg .u64 t; cvta.to.shared.u64 t, %1; cvt.u32.u64 %0, t; }" : "=r"(a) : "l"(p));
    return a;
}
__device__ __forceinline__ void cp16(uint32_t dst, const void* src) {
    asm volatile("cp.async.ca.shared.global [%0], [%1], 16;" :: "r"(dst), "l"(src));
}
__device__ __forceinline__ void cp4(uint32_t dst, const void* src) {
    asm volatile("cp.async.ca.shared.global [%0], [%1], 4;" :: "r"(dst), "l"(src));
}
__device__ __forceinline__ void cp_commit() { asm volatile("cp.async.commit_group;"); }
template <int N>
__device__ __forceinline__ void cp_wait() { asm volatile("cp.async.wait_group %0;" :: "n"(N)); }

// ---------------- single fused kernel ----------------
__global__ void __launch_bounds__(256, 1)
fm_gemm(const float* __restrict__ data,
        const float* __restrict__ embed,
        const float* __restrict__ bias,
        const float* __restrict__ gbias,
        float* __restrict__ out)
{
    __shared__ float As[2][128 * A_STRIDE];   // 36 KB
    __shared__ float Bs[2][KC * B_STRIDE];    // 10 KB
    __shared__ unsigned s_last;

    const int t = threadIdx.x;
    const int w = t >> 5, lane = t & 31;
    const int g = lane >> 2, ctg = lane & 3;
    const int mtile = blockIdx.x & 7;
    const int kbase = (blockIdx.x >> 3) * K_PER_CTA;
    const float* arow0 = data + (size_t)(mtile * 128) * FF + kbase;

    // zero the pad columns (n=33..39) of both B buffers ONCE; cp.async never writes them
    for (int i = t; i < 2 * KC * 7; i += 256) {
        const int buf = i >= KC * 7;
        const int j = i - buf * KC * 7;
        const int k = j / 7, n = 33 + (j - k * 7);
        Bs[buf][k * B_STRIDE + n] = 0.f;
    }

    auto loadA = [&](int c, int buf) {
        #pragma unroll
        for (int i = 0; i < 4; i++) {
            const int idx = t + i * 256;           // 1024 float4
            const int row = idx >> 3, kq = (idx & 7) << 2;
            cp16(smem_u32(&As[buf][row * A_STRIDE + kq]),
                 arow0 + (size_t)row * FF + c * KC + kq);
        }
    };
    // B[k][0:32] = embed row (k-major, contiguous); B[k][32] = bias[k]
    auto loadB = [&](int c, int buf) {
        const int k = t >> 3, q4 = (t & 7) << 2;   // 256 threads -> 32k x 8 float4
        cp16(smem_u32(&Bs[buf][k * B_STRIDE + q4]),
             embed + (size_t)(kbase + c * KC + k) * DD + q4);
        if (t < KC)
            cp4(smem_u32(&Bs[buf][t * B_STRIDE + 32]), bias + kbase + c * KC + t);
    };

    float acc[NT][4];
    #pragma unroll
    for (int nt = 0; nt < NT; nt++)
        #pragma unroll
        for (int j = 0; j < 4; j++) acc[nt][j] = 0.f;

    loadA(0, 0); loadB(0, 0); cp_commit();

    for (int ch = 0; ch < NCHUNK; ch++) {
        const int buf = ch & 1;
        if (ch + 1 < NCHUNK) {
            loadA(ch + 1, buf ^ 1); loadB(ch + 1, buf ^ 1); cp_commit();
            cp_wait<1>();
        } else {
            cp_wait<0>();
        }
        __syncthreads();

        const float* Aw = &As[buf][(w * 16) * A_STRIDE];
        const float* Bw = &Bs[buf][0];

        #pragma unroll
        for (int ks = 0; ks < 4; ks++) {
            const int k0 = ks * 8;
            const uint32_t a0 = __float_as_uint(Aw[g * A_STRIDE + k0 + ctg]);
            const uint32_t a1 = __float_as_uint(Aw[(g + 8) * A_STRIDE + k0 + ctg]);
            const uint32_t a2 = __float_as_uint(Aw[g * A_STRIDE + k0 + ctg + 4]);
            const uint32_t a3 = __float_as_uint(Aw[(g + 8) * A_STRIDE + k0 + ctg + 4]);
            #pragma unroll
            for (int nt = 0; nt < NT; nt++) {
                const uint32_t b0 = __float_as_uint(Bw[(k0 + ctg) * B_STRIDE + nt * 8 + g]);
                const uint32_t b1 = __float_as_uint(Bw[(k0 + ctg + 4) * B_STRIDE + nt * 8 + g]);
                asm volatile(
                    "mma.sync.aligned.m16n8k8.row.col.f32.tf32.tf32.f32 "
                    "{%0,%1,%2,%3}, {%4,%5,%6,%7}, {%8,%9}, {%0,%1,%2,%3};"
                    : "+f"(acc[nt][0]), "+f"(acc[nt][1]), "+f"(acc[nt][2]), "+f"(acc[nt][3])
                    : "r"(a0), "r"(a1), "r"(a2), "r"(a3), "r"(b0), "r"(b1));
            }
        }
        __syncthreads();
    }

    // ---- epilogue: spread-address atomics into global accumulators ----
    const int mbase = mtile * 128 + w * 16;
    #pragma unroll
    for (int nt = 0; nt < NT; nt++) {
        #pragma unroll
        for (int j = 0; j < 4; j++) {
            const int n = nt * 8 + 2 * ctg + (j & 1);
            const int m = mbase + g + ((j >> 1) << 3);
            if (n < DD)
                atomicAdd(&g_s[(size_t)m * DD + n], acc[nt][j]);
            else if (n == DD)
                atomicAdd(&g_b[m], acc[nt][j]);
        }
    }

    // ---- last k-split CTA per mtile finishes its 128 rows (threadfence reduction) ----
    __threadfence();
    __syncthreads();
    if (t == 0)
        s_last = (atomicAdd(&g_cnt[mtile], 1u) == KSPLITS - 1);
    __syncthreads();

    if (s_last) {
        const float gbv = gbias[0];
        #pragma unroll
        for (int i = 0; i < 16; i++) {
            const int row = mtile * 128 + w * 16 + i;
            const float s = g_s[(size_t)row * DD + lane];
            float v = s * s;
            if (lane == 0) v += g_b[row];
            #pragma unroll
            for (int o = 16; o; o >>= 1)
                v += __shfl_xor_sync(0xffffffffu, v, o);
            if (lane == 0) {
                out[row] = 1.0f / (1.0f + __expf(-(gbv + v)));
                g_b[row] = 0.f;                       // reset for next replay
            }
            g_s[(size_t)row * DD + lane] = 0.f;       // reset for next replay
        }
        if (t == 0) g_cnt[mtile] = 0u;                // reset counter
    }
}

extern "C" void kernel_launch(void* const* d_in, const int* in_sizes, int n_in,
                              void* d_out, int out_size)
{
    const float* data  = (const float*)d_in[0];
    const float* embed = (const float*)d_in[1];
    const float* bias  = (const float*)d_in[2];
    const float* gb    = (const float*)d_in[3];
    float* out = (float*)d_out;

    fm_gemm<<<MTILES * KSPLITS, 256>>>(data, embed, bias, gb, out);
}

// round 6
// speedup vs baseline: 1.4310x; 1.4310x over previous
#include <cuda_runtime.h>
#include <cstdint>
#include <cstddef>

#define BB 1024
#define FF 4096
#define DD 32
#define NB 40            // GEMM N: 0-31 embed dims, 32 bias, 33-39 zero pad
#define NT 5             // n-tiles of 8
#define MTILES 8
#define KSPLITS 32
#define K_PER_CTA 128
#define KC 32            // K per chunk
#define NCHUNK 4         // chunks per CTA
#define A_STRIDE 36      // smem floats per A row (conflict-free, 16B aligned)
#define B_STRIDE 40      // smem floats per B k-row (conflict-free, 16B aligned)

__device__ float g_B2[(size_t)FF * NB];  // [k][n] weight matrix
__device__ float g_s[(size_t)BB * DD];   // accumulated s[row][d] (zero-init, self-zeroing)
__device__ float g_b[(size_t)BB];        // accumulated bias_term[row]

__device__ __forceinline__ uint32_t smem_u32(const void* p) {
    uint32_t a;
    asm("{ .reg .u64 t; cvta.to.shared.u64 t, %1; cvt.u32.u64 %0, t; }" : "=r"(a) : "l"(p));
    return a;
}
__device__ __forceinline__ void cp16(uint32_t dst, const void* src) {
    asm volatile("cp.async.ca.shared.global [%0], [%1], 16;" :: "r"(dst), "l"(src));
}
__device__ __forceinline__ void cp_commit() { asm volatile("cp.async.commit_group;"); }
template <int N>
__device__ __forceinline__ void cp_wait() { asm volatile("cp.async.wait_group %0;" :: "n"(N)); }

// ---------------- prep: g_B2[k][:] = [embed[k][:], bias[k], 0 x 7] (pure copy) ----------------
__global__ void __launch_bounds__(256)
fm_prep(const float* __restrict__ embed, const float* __restrict__ bias)
{
    const int idx = blockIdx.x * 256 + threadIdx.x;   // 32768 threads, 8 per row
    const int row = idx >> 3, q = (idx & 7) << 2;
    const float4 v = *reinterpret_cast<const float4*>(embed + (size_t)row * DD + q);
    *reinterpret_cast<float4*>(g_B2 + (size_t)row * NB + q) = v;
    if (q == 0) {
        *reinterpret_cast<float4*>(g_B2 + (size_t)row * NB + 32) =
            make_float4(bias[row], 0.f, 0.f, 0.f);
        *reinterpret_cast<float4*>(g_B2 + (size_t)row * NB + 36) =
            make_float4(0.f, 0.f, 0.f, 0.f);
    }
}

// ---------------- GEMM: tf32 mma.sync, 2-stage cp.async pipeline, 2 CTAs/SM ----------------
__global__ void __launch_bounds__(256, 2)
fm_gemm(const float* __restrict__ data)
{
    __shared__ float As[2][128 * A_STRIDE];   // 36 KB
    __shared__ float Bs[2][KC * B_STRIDE];    // 10 KB

    const int t = threadIdx.x;
    const int w = t >> 5, lane = t & 31;
    const int g = lane >> 2, ctg = lane & 3;
    const int mtile = blockIdx.x & 7;
    const int kbase = (blockIdx.x >> 3) * K_PER_CTA;
    const float* arow0 = data + (size_t)(mtile * 128) * FF + kbase;

    auto loadA = [&](int c, int buf) {
        #pragma unroll
        for (int i = 0; i < 4; i++) {
            const int idx = t + i * 256;           // 1024 float4
            const int row = idx >> 3, kq = (idx & 7) << 2;
            cp16(smem_u32(&As[buf][row * A_STRIDE + kq]),
                 arow0 + (size_t)row * FF + c * KC + kq);
        }
    };
    auto loadB = [&](int c, int buf) {
        const float* src = g_B2 + (size_t)(kbase + c * KC) * NB;  // 320 contiguous float4
        cp16(smem_u32(&Bs[buf][t * 4]), src + t * 4);
        if (t < 64)
            cp16(smem_u32(&Bs[buf][(t + 256) * 4]), src + (t + 256) * 4);
    };

    float acc[NT][4];
    #pragma unroll
    for (int nt = 0; nt < NT; nt++)
        #pragma unroll
        for (int j = 0; j < 4; j++) acc[nt][j] = 0.f;

    loadA(0, 0); loadB(0, 0); cp_commit();

    #pragma unroll
    for (int ch = 0; ch < NCHUNK; ch++) {
        const int buf = ch & 1;
        if (ch + 1 < NCHUNK) {
            loadA(ch + 1, buf ^ 1); loadB(ch + 1, buf ^ 1); cp_commit();
            cp_wait<1>();
        } else {
            cp_wait<0>();
        }
        __syncthreads();

        const float* Aw = &As[buf][(w * 16) * A_STRIDE];
        const float* Bw = &Bs[buf][0];

        #pragma unroll
        for (int ks = 0; ks < 4; ks++) {
            const int k0 = ks * 8;
            const uint32_t a0 = __float_as_uint(Aw[g * A_STRIDE + k0 + ctg]);
            const uint32_t a1 = __float_as_uint(Aw[(g + 8) * A_STRIDE + k0 + ctg]);
            const uint32_t a2 = __float_as_uint(Aw[g * A_STRIDE + k0 + ctg + 4]);
            const uint32_t a3 = __float_as_uint(Aw[(g + 8) * A_STRIDE + k0 + ctg + 4]);
            #pragma unroll
            for (int nt = 0; nt < NT; nt++) {
                const uint32_t b0 = __float_as_uint(Bw[(k0 + ctg) * B_STRIDE + nt * 8 + g]);
                const uint32_t b1 = __float_as_uint(Bw[(k0 + ctg + 4) * B_STRIDE + nt * 8 + g]);
                asm volatile(
                    "mma.sync.aligned.m16n8k8.row.col.f32.tf32.tf32.f32 "
                    "{%0,%1,%2,%3}, {%4,%5,%6,%7}, {%8,%9}, {%0,%1,%2,%3};"
                    : "+f"(acc[nt][0]), "+f"(acc[nt][1]), "+f"(acc[nt][2]), "+f"(acc[nt][3])
                    : "r"(a0), "r"(a1), "r"(a2), "r"(a3), "r"(b0), "r"(b1));
            }
        }
        __syncthreads();
    }

    // epilogue: one atomic pass; cols 33..39 are exact zeros (discard)
    const int mbase = mtile * 128 + w * 16;
    #pragma unroll
    for (int nt = 0; nt < NT; nt++) {
        #pragma unroll
        for (int j = 0; j < 4; j++) {
            const int n = nt * 8 + 2 * ctg + (j & 1);
            const int m = mbase + g + ((j >> 1) << 3);
            if (n < DD)
                atomicAdd(&g_s[(size_t)m * DD + n], acc[nt][j]);
            else if (n == DD)
                atomicAdd(&g_b[m], acc[nt][j]);
        }
    }
}

// ---------------- finisher: sigmoid + self-zero accumulators ----------------
__global__ void __launch_bounds__(256)
fm_finish(const float* __restrict__ gbias, float* __restrict__ out)
{
    const int w = threadIdx.x >> 5, lane = threadIdx.x & 31;
    const int row = blockIdx.x * 8 + w;

    const float s = g_s[(size_t)row * DD + lane];
    float t = s * s;
    if (lane == 0) t += g_b[row];

    #pragma unroll
    for (int o = 16; o; o >>= 1)
        t += __shfl_xor_sync(0xffffffffu, t, o);

    if (lane == 0) {
        out[row] = 1.0f / (1.0f + __expf(-(gbias[0] + t)));
        g_b[row] = 0.f;
    }
    g_s[(size_t)row * DD + lane] = 0.f;   // reset for next replay
}

extern "C" void kernel_launch(void* const* d_in, const int* in_sizes, int n_in,
                              void* d_out, int out_size)
{
    const float* data  = (const float*)d_in[0];
    const float* embed = (const float*)d_in[1];
    const float* bias  = (const float*)d_in[2];
    const float* gb    = (const float*)d_in[3];
    float* out = (float*)d_out;

    fm_prep<<<BB * DD / 256 / 4 * 8, 256>>>(embed, bias);   // 128 blocks
    fm_gemm<<<MTILES * KSPLITS, 256>>>(data);
    fm_finish<<<BB / 8, 256>>>(gb, out);
}

// round 7
// speedup vs baseline: 1.6810x; 1.1747x over previous
#include <cuda_runtime.h>
#include <cstdint>
#include <cstddef>

#define BB 1024
#define FF 4096
#define DD 32
#define NT 5             // n-tiles of 8: n 0-31 embed, 32 bias, 33-39 zero pad
#define MTILES 8
#define KSPLITS 32
#define K_PER_CTA 128
#define KC 32            // K per chunk
#define NCHUNK 4         // chunks per CTA
#define A_STRIDE 36      // smem floats per A row (conflict-free, 16B aligned)
#define B_STRIDE 40      // smem floats per B k-row (conflict-free, 16B aligned)

__device__ float g_s[(size_t)BB * DD];   // accumulated s[row][d] (static zero; self-zeroing)
__device__ float g_b[(size_t)BB];        // accumulated bias_term[row]

__device__ __forceinline__ uint32_t smem_u32(const void* p) {
    uint32_t a;
    asm("{ .reg .u64 t; cvta.to.shared.u64 t, %1; cvt.u32.u64 %0, t; }" : "=r"(a) : "l"(p));
    return a;
}
__device__ __forceinline__ void cp16(uint32_t dst, const void* src) {
    asm volatile("cp.async.ca.shared.global [%0], [%1], 16;" :: "r"(dst), "l"(src));
}
__device__ __forceinline__ void cp4(uint32_t dst, const void* src) {
    asm volatile("cp.async.ca.shared.global [%0], [%1], 4;" :: "r"(dst), "l"(src));
}
__device__ __forceinline__ void cp_commit() { asm volatile("cp.async.commit_group;"); }
template <int N>
__device__ __forceinline__ void cp_wait() { asm volatile("cp.async.wait_group %0;" :: "n"(N)); }

// ---------------- GEMM: tf32 mma.sync, B loaded directly from embed/bias ----------------
__global__ void __launch_bounds__(256, 2)
fm_gemm(const float* __restrict__ data,
        const float* __restrict__ embed,
        const float* __restrict__ bias)
{
    __shared__ float As[2][128 * A_STRIDE];   // 36 KB
    __shared__ float Bs[2][KC * B_STRIDE];    // 10 KB

    const int t = threadIdx.x;
    const int w = t >> 5, lane = t & 31;
    const int g = lane >> 2, ctg = lane & 3;
    const int mtile = blockIdx.x & 7;
    const int kbase = (blockIdx.x >> 3) * K_PER_CTA;
    const float* arow0 = data + (size_t)(mtile * 128) * FF + kbase;

    // zero pad columns (n=33..39) of both B buffers ONCE; cp.async never writes them
    for (int i = t; i < 2 * KC * 7; i += 256) {
        const int buf = i >= KC * 7;
        const int j = i - buf * KC * 7;
        const int k = j / 7, n = 33 + (j - k * 7);
        Bs[buf][k * B_STRIDE + n] = 0.f;
    }

    auto loadA = [&](int c, int buf) {
        #pragma unroll
        for (int i = 0; i < 4; i++) {
            const int idx = t + i * 256;           // 1024 float4
            const int row = idx >> 3, kq = (idx & 7) << 2;
            cp16(smem_u32(&As[buf][row * A_STRIDE + kq]),
                 arow0 + (size_t)row * FF + c * KC + kq);
        }
    };
    // B[k][0:32] = embed[kbase+c*KC+k][:] (k-major contiguous); B[k][32] = bias[k]
    auto loadB = [&](int c, int buf) {
        const int k = t >> 3, q4 = (t & 7) << 2;   // 256 threads -> 32 k-rows x 8 float4
        cp16(smem_u32(&Bs[buf][k * B_STRIDE + q4]),
             embed + (size_t)(kbase + c * KC + k) * DD + q4);
        if (t < KC)
            cp4(smem_u32(&Bs[buf][t * B_STRIDE + 32]), bias + kbase + c * KC + t);
    };

    float acc[NT][4];
    #pragma unroll
    for (int nt = 0; nt < NT; nt++)
        #pragma unroll
        for (int j = 0; j < 4; j++) acc[nt][j] = 0.f;

    loadA(0, 0); loadB(0, 0); cp_commit();

    #pragma unroll
    for (int ch = 0; ch < NCHUNK; ch++) {
        const int buf = ch & 1;
        if (ch + 1 < NCHUNK) {
            loadA(ch + 1, buf ^ 1); loadB(ch + 1, buf ^ 1); cp_commit();
            cp_wait<1>();
        } else {
            cp_wait<0>();
        }
        __syncthreads();

        const float* Aw = &As[buf][(w * 16) * A_STRIDE];
        const float* Bw = &Bs[buf][0];

        #pragma unroll
        for (int ks = 0; ks < 4; ks++) {
            const int k0 = ks * 8;
            const uint32_t a0 = __float_as_uint(Aw[g * A_STRIDE + k0 + ctg]);
            const uint32_t a1 = __float_as_uint(Aw[(g + 8) * A_STRIDE + k0 + ctg]);
            const uint32_t a2 = __float_as_uint(Aw[g * A_STRIDE + k0 + ctg + 4]);
            const uint32_t a3 = __float_as_uint(Aw[(g + 8) * A_STRIDE + k0 + ctg + 4]);
            #pragma unroll
            for (int nt = 0; nt < NT; nt++) {
                const uint32_t b0 = __float_as_uint(Bw[(k0 + ctg) * B_STRIDE + nt * 8 + g]);
                const uint32_t b1 = __float_as_uint(Bw[(k0 + ctg + 4) * B_STRIDE + nt * 8 + g]);
                asm volatile(
                    "mma.sync.aligned.m16n8k8.row.col.f32.tf32.tf32.f32 "
                    "{%0,%1,%2,%3}, {%4,%5,%6,%7}, {%8,%9}, {%0,%1,%2,%3};"
                    : "+f"(acc[nt][0]), "+f"(acc[nt][1]), "+f"(acc[nt][2]), "+f"(acc[nt][3])
                    : "r"(a0), "r"(a1), "r"(a2), "r"(a3), "r"(b0), "r"(b1));
            }
        }
        __syncthreads();
    }

    // epilogue: one spread-address atomic pass; cols 33..39 are exact zeros (discard)
    const int mbase = mtile * 128 + w * 16;
    #pragma unroll
    for (int nt = 0; nt < NT; nt++) {
        #pragma unroll
        for (int j = 0; j < 4; j++) {
            const int n = nt * 8 + 2 * ctg + (j & 1);
            const int m = mbase + g + ((j >> 1) << 3);
            if (n < DD)
                atomicAdd(&g_s[(size_t)m * DD + n], acc[nt][j]);
            else if (n == DD)
                atomicAdd(&g_b[m], acc[nt][j]);
        }
    }
}

// ---------------- finisher: sigmoid + self-zero accumulators ----------------
__global__ void __launch_bounds__(256)
fm_finish(const float* __restrict__ gbias, float* __restrict__ out)
{
    const int w = threadIdx.x >> 5, lane = threadIdx.x & 31;
    const int row = blockIdx.x * 8 + w;

    const float s = g_s[(size_t)row * DD + lane];
    float t = s * s;
    if (lane == 0) t += g_b[row];

    #pragma unroll
    for (int o = 16; o; o >>= 1)
        t += __shfl_xor_sync(0xffffffffu, t, o);

    if (lane == 0) {
        out[row] = 1.0f / (1.0f + __expf(-(gbias[0] + t)));
        g_b[row] = 0.f;
    }
    g_s[(size_t)row * DD + lane] = 0.f;   // reset for next replay
}

extern "C" void kernel_launch(void* const* d_in, const int* in_sizes, int n_in,
                              void* d_out, int out_size)
{
    const float* data  = (const float*)d_in[0];
    const float* embed = (const float*)d_in[1];
    const float* bias  = (const float*)d_in[2];
    const float* gb    = (const float*)d_in[3];
    float* out = (float*)d_out;

    fm_gemm<<<MTILES * KSPLITS, 256>>>(data, embed, bias);
    fm_finish<<<BB / 8, 256>>>(gb, out);
}